// round 2
// baseline (speedup 1.0000x reference)
#include <cuda_runtime.h>
#include <cstdint>
#include <cstddef>

#define BB 16384
#define FF 39
#define EE 16
#define PP 741
#define IN_DIM 2223
#define WOFF_N 1482
#define VOCAB 26000
#define LRC 0.001f
#define MU0 (1.0f/39.0f)
#define RB 4

// ---------------- scratch (device globals; no allocation) ----------------
__device__ float g_h[(size_t)BB * IN_DIM];   // [B, 2223]
__device__ float g_lin[BB];
__device__ float g_a1[IN_DIM];
__device__ float g_c1[IN_DIM];
__device__ float g_h2[BB * 100];
__device__ float g_p2s[64 * 100];
__device__ float g_p2q[64 * 100];
__device__ float g_a2[100];
__device__ float g_c2[100];
__device__ float g_h3[BB * 100];

// ---------------- front kernel: gather + meta step + sparsemax + pairs ----
__global__ __launch_bounds__(256) void front_kernel(
    const int* __restrict__ x, const float* __restrict__ emb,
    const float* __restrict__ linw, const float* __restrict__ w0,
    const float* __restrict__ kern)
{
    __shared__ float s_vx[RB][FF][EE + 1];   // padded to kill bank conflicts
    __shared__ float s_t [RB][FF][EE + 1];   // wv0, then wv1
    __shared__ float s_w1[RB][FF][FF];
    __shared__ float s_z [RB][FF];
    __shared__ float s_zs[RB][FF];
    __shared__ float s_mu[RB][FF];
    __shared__ float s_lv[RB][FF];
    __shared__ float s_tau[RB];

    const int tid = threadIdx.x;
    const int b0  = blockIdx.x * RB;

    // gather embeddings (float4 per thread-task) + lin weights
    for (int t = tid; t < RB * FF * 4; t += 256) {
        int r   = t / (FF * 4);
        int rem = t - r * (FF * 4);
        int f   = rem >> 2;
        int c   = rem & 3;
        int xi  = x[(b0 + r) * FF + f] + f * VOCAB;
        float4 v = reinterpret_cast<const float4*>(emb)[(size_t)xi * 4 + c];
        s_vx[r][f][c * 4 + 0] = v.x;
        s_vx[r][f][c * 4 + 1] = v.y;
        s_vx[r][f][c * 4 + 2] = v.z;
        s_vx[r][f][c * 4 + 3] = v.w;
        if (c == 0) s_lv[r][f] = linw[xi];
    }
    __syncthreads();

    // wv0 = w0 @ vx
    for (int t = tid; t < RB * FF * EE; t += 256) {
        int r = t / (FF * EE);
        int rem = t - r * (FF * EE);
        int i = rem / EE, e = rem - i * EE;
        float acc = 0.f;
        #pragma unroll
        for (int j = 0; j < FF; j++) acc = fmaf(w0[i * FF + j], s_vx[r][j][e], acc);
        s_t[r][i][e] = acc;
    }
    __syncthreads();

    // w1 = w0 - (LR*mu0) * (wv0 vx^T), diag = -1
    for (int t = tid; t < RB * FF * FF; t += 256) {
        int r = t / (FF * FF);
        int rem = t - r * (FF * FF);
        int i = rem / FF, j = rem - i * FF;
        float v;
        if (i == j) v = -1.0f;
        else {
            float d = 0.f;
            #pragma unroll
            for (int e = 0; e < EE; e++) d = fmaf(s_t[r][i][e], s_vx[r][j][e], d);
            v = w0[i * FF + j] - (LRC * MU0) * d;
        }
        s_w1[r][i][j] = v;
    }
    __syncthreads();

    // wv1 = w1 @ vx  (reuse s_t)
    for (int t = tid; t < RB * FF * EE; t += 256) {
        int r = t / (FF * EE);
        int rem = t - r * (FF * EE);
        int i = rem / EE, e = rem - i * EE;
        float acc = 0.f;
        #pragma unroll
        for (int j = 0; j < FF; j++) acc = fmaf(s_w1[r][i][j], s_vx[r][j][e], acc);
        s_t[r][i][e] = acc;
    }
    __syncthreads();

    // z = mu0 - LR * 0.5 * ||wv1_i||^2
    for (int t = tid; t < RB * FF; t += 256) {
        int r = t / FF, i = t - r * FF;
        float d = 0.f;
        #pragma unroll
        for (int e = 0; e < EE; e++) { float v = s_t[r][i][e]; d = fmaf(v, v, d); }
        s_z[r][i] = MU0 - LRC * 0.5f * d;
    }
    __syncthreads();

    // sort desc via rank counting (stable tie-break)
    for (int t = tid; t < RB * FF; t += 256) {
        int r = t / FF, i = t - r * FF;
        float zi = s_z[r][i];
        int rank = 0;
        #pragma unroll
        for (int j = 0; j < FF; j++) {
            float zj = s_z[r][j];
            rank += (zj > zi) || (zj == zi && j < i);
        }
        s_zs[r][rank] = zi;
    }
    __syncthreads();

    // sparsemax threshold per row (+ lin sum)
    if (tid < RB) {
        int r = tid;
        float z0 = s_zs[r][0];
        float taus[FF];
        float cs = 0.f;
        #pragma unroll
        for (int j = 0; j < FF; j++) {
            cs += s_zs[r][j] - z0;
            taus[j] = (cs - 1.0f) / (float)(j + 1);
        }
        int k = 0;
        #pragma unroll
        for (int j = 0; j < FF; j++) k += (s_zs[r][j] - z0) > taus[j];
        s_tau[r] = taus[k - 1] + z0;

        float ls = 0.f;
        #pragma unroll
        for (int f = 0; f < FF; f++) ls += s_lv[r][f];
        g_lin[b0 + r] = ls;
    }
    __syncthreads();

    for (int t = tid; t < RB * FF; t += 256) {
        int r = t / FF, i = t - r * FF;
        s_mu[r][i] = fmaxf(s_z[r][i] - s_tau[r], 0.f);
    }
    __syncthreads();

    // woff: flat indices 1 + 40*(m/39) + m%39  (off-diagonals of mu*w1)
    for (int t = tid; t < RB * WOFF_N; t += 256) {
        int r = t / WOFF_N;
        int m = t - r * WOFF_N;
        int fl = 1 + 40 * (m / 39) + (m % 39);
        int i = fl / 39, j = fl - i * 39;
        g_h[(size_t)(b0 + r) * IN_DIM + m] = s_mu[r][i] * s_w1[r][i][j];
    }

    // pairwise bilinear: ox[p] = vx_i^T K_p vx_j for each of 4 rows
    for (int p = tid; p < PP; p += 256) {
        int i = 0, pp = p;
        while (pp >= FF - 1 - i) { pp -= FF - 1 - i; i++; }
        int j = i + 1 + pp;
        const float* Kp = kern + (size_t)p * EE * EE;
        #pragma unroll
        for (int g = 0; g < RB; g += 2) {
            float T[2][EE];
            #pragma unroll
            for (int f2 = 0; f2 < EE; f2++) { T[0][f2] = 0.f; T[1][f2] = 0.f; }
            #pragma unroll 4
            for (int e = 0; e < EE; e++) {
                float kr[EE];
                #pragma unroll
                for (int c = 0; c < 4; c++) {
                    float4 kv = reinterpret_cast<const float4*>(Kp)[e * 4 + c];
                    kr[c * 4 + 0] = kv.x; kr[c * 4 + 1] = kv.y;
                    kr[c * 4 + 2] = kv.z; kr[c * 4 + 3] = kv.w;
                }
                float a0 = s_vx[g + 0][i][e];
                float a1 = s_vx[g + 1][i][e];
                #pragma unroll
                for (int f2 = 0; f2 < EE; f2++) {
                    T[0][f2] = fmaf(a0, kr[f2], T[0][f2]);
                    T[1][f2] = fmaf(a1, kr[f2], T[1][f2]);
                }
            }
            #pragma unroll
            for (int q = 0; q < 2; q++) {
                float acc = 0.f;
                #pragma unroll
                for (int f2 = 0; f2 < EE; f2++)
                    acc = fmaf(T[q][f2], s_vx[g + q][j][f2], acc);
                g_h[(size_t)(b0 + g + q) * IN_DIM + WOFF_N + p] = acc;
            }
        }
    }
}

// ---------------- BN1 column stats (deterministic) ----------------
__global__ __launch_bounds__(256) void bn1_reduce(const float* __restrict__ gam,
                                                  const float* __restrict__ bet)
{
    __shared__ float shs[8][32];
    __shared__ float shq[8][32];
    int lane = threadIdx.x & 31;
    int rl   = threadIdx.x >> 5;          // 0..7
    int col  = blockIdx.x * 32 + lane;
    float s = 0.f, q = 0.f;
    if (col < IN_DIM) {
        for (int r = rl; r < BB; r += 8) {
            float v = g_h[(size_t)r * IN_DIM + col];
            s += v; q = fmaf(v, v, q);
        }
    }
    shs[rl][lane] = s; shq[rl][lane] = q;
    __syncthreads();
    if (rl == 0 && col < IN_DIM) {
        #pragma unroll
        for (int t = 1; t < 8; t++) { s += shs[t][lane]; q += shq[t][lane]; }
        float m   = s * (1.0f / BB);
        float var = q * (1.0f / BB) - m * m;
        float a   = gam[col] * rsqrtf(var + 1e-5f);
        g_a1[col] = a;
        g_c1[col] = bet[col] - m * a;
    }
}

// ---------------- generic MLP GEMM: out = relu((A*a+c) @ W^T + b) --------
// A: [B, K] (row stride K), W: [100, K], out: [B, 100]
__global__ __launch_bounds__(256) void mlp_gemm(
    const float* __restrict__ A, int K,
    const float* __restrict__ avec, const float* __restrict__ cvec,
    const float* __restrict__ W, const float* __restrict__ bias,
    float* __restrict__ out)
{
    __shared__ float sA[16][65];
    __shared__ float sW[16][113];
    const int bm = blockIdx.x * 64;
    const int tx = threadIdx.x & 15;
    const int ty = threadIdx.x >> 4;
    float acc[4][7];
    #pragma unroll
    for (int i2 = 0; i2 < 4; i2++)
        #pragma unroll
        for (int j2 = 0; j2 < 7; j2++) acc[i2][j2] = 0.f;

    for (int k0 = 0; k0 < K; k0 += 16) {
        for (int t = threadIdx.x; t < 64 * 16; t += 256) {
            int m = t >> 4, kk = t & 15;
            int k = k0 + kk;
            float v = 0.f;
            if (k < K) v = fmaf(A[(size_t)(bm + m) * K + k], avec[k], cvec[k]);
            sA[kk][m] = v;
        }
        for (int t = threadIdx.x; t < 112 * 16; t += 256) {
            int n = t >> 4, kk = t & 15;
            int k = k0 + kk;
            sW[kk][n] = (n < 100 && k < K) ? W[n * K + k] : 0.f;
        }
        __syncthreads();
        #pragma unroll
        for (int kk = 0; kk < 16; kk++) {
            float ra[4], rw[7];
            #pragma unroll
            for (int i2 = 0; i2 < 4; i2++) ra[i2] = sA[kk][ty + 16 * i2];
            #pragma unroll
            for (int j2 = 0; j2 < 7; j2++) rw[j2] = sW[kk][tx + 16 * j2];
            #pragma unroll
            for (int i2 = 0; i2 < 4; i2++)
                #pragma unroll
                for (int j2 = 0; j2 < 7; j2++)
                    acc[i2][j2] = fmaf(ra[i2], rw[j2], acc[i2][j2]);
        }
        __syncthreads();
    }
    #pragma unroll
    for (int i2 = 0; i2 < 4; i2++) {
        int m = bm + ty + 16 * i2;
        #pragma unroll
        for (int j2 = 0; j2 < 7; j2++) {
            int n = tx + 16 * j2;
            if (n < 100) out[m * 100 + n] = fmaxf(acc[i2][j2] + bias[n], 0.f);
        }
    }
}

// ---------------- BN2 two-level deterministic reduction -------------------
__global__ __launch_bounds__(128) void bn2_partial()
{
    int c  = threadIdx.x;                  // 0..127, valid < 100
    int r0 = blockIdx.x * 256;
    if (c < 100) {
        float s = 0.f, q = 0.f;
        for (int r = r0; r < r0 + 256; r++) {
            float v = g_h2[r * 100 + c];
            s += v; q = fmaf(v, v, q);
        }
        g_p2s[blockIdx.x * 100 + c] = s;
        g_p2q[blockIdx.x * 100 + c] = q;
    }
}

__global__ __launch_bounds__(128) void bn2_final(const float* __restrict__ gam,
                                                 const float* __restrict__ bet)
{
    int c = threadIdx.x;
    if (c < 100) {
        float s = 0.f, q = 0.f;
        for (int i = 0; i < 64; i++) { s += g_p2s[i * 100 + c]; q += g_p2q[i * 100 + c]; }
        float m   = s * (1.0f / BB);
        float var = q * (1.0f / BB) - m * m;
        float a   = gam[c] * rsqrtf(var + 1e-5f);
        g_a2[c] = a;
        g_c2[c] = bet[c] - m * a;
    }
}

// ---------------- fc3 + lin ----------------------------------------------
__global__ __launch_bounds__(256) void out_kernel(const float* __restrict__ w3,
                                                  const float* __restrict__ b3,
                                                  float* __restrict__ out)
{
    int wrp  = (blockIdx.x * 256 + threadIdx.x) >> 5;
    int lane = threadIdx.x & 31;
    if (wrp < BB) {
        float s = 0.f;
        for (int k = lane; k < 100; k += 32)
            s = fmaf(g_h3[wrp * 100 + k], w3[k], s);
        #pragma unroll
        for (int o = 16; o > 0; o >>= 1) s += __shfl_xor_sync(0xffffffffu, s, o);
        if (lane == 0) out[wrp] = s + b3[0] + g_lin[wrp];
    }
}

// ---------------- launch ---------------------------------------------------
extern "C" void kernel_launch(void* const* d_in, const int* in_sizes, int n_in,
                              void* d_out, int out_size)
{
    const int*   x     = (const int*)  d_in[0];
    const float* emb   = (const float*)d_in[1];
    const float* linw  = (const float*)d_in[2];
    const float* w0    = (const float*)d_in[3];
    const float* kern  = (const float*)d_in[4];
    const float* bn1g  = (const float*)d_in[5];
    const float* bn1b  = (const float*)d_in[6];
    const float* fc1w  = (const float*)d_in[7];
    const float* fc1b  = (const float*)d_in[8];
    const float* bn2g  = (const float*)d_in[9];
    const float* bn2b  = (const float*)d_in[10];
    const float* fc2w  = (const float*)d_in[11];
    const float* fc2b  = (const float*)d_in[12];
    const float* fc3w  = (const float*)d_in[13];
    const float* fc3b  = (const float*)d_in[14];
    float* out = (float*)d_out;
    (void)in_sizes; (void)n_in; (void)out_size;

    float *gh, *gh2, *gh3, *ga1, *gc1, *ga2, *gc2;
    cudaGetSymbolAddress((void**)&gh,  g_h);
    cudaGetSymbolAddress((void**)&gh2, g_h2);
    cudaGetSymbolAddress((void**)&gh3, g_h3);
    cudaGetSymbolAddress((void**)&ga1, g_a1);
    cudaGetSymbolAddress((void**)&gc1, g_c1);
    cudaGetSymbolAddress((void**)&ga2, g_a2);
    cudaGetSymbolAddress((void**)&gc2, g_c2);

    front_kernel<<<BB / RB, 256>>>(x, emb, linw, w0, kern);
    bn1_reduce  <<<(IN_DIM + 31) / 32, 256>>>(bn1g, bn1b);
    mlp_gemm    <<<BB / 64, 256>>>(gh,  IN_DIM, ga1, gc1, fc1w, fc1b, gh2);
    bn2_partial <<<64, 128>>>();
    bn2_final   <<<1, 128>>>(bn2g, bn2b);
    mlp_gemm    <<<BB / 64, 256>>>(gh2, 100,    ga2, gc2, fc2w, fc2b, gh3);
    out_kernel  <<<(BB * 32 + 255) / 256, 256>>>(fc3w, fc3b, out);
}

// round 3
// speedup vs baseline: 1.8364x; 1.8364x over previous
#include <cuda_runtime.h>
#include <cstdint>
#include <cstddef>

#define BB 16384
#define FF 39
#define EE 16
#define PP 741
#define IN_DIM 2223
#define WOFF_N 1482
#define VOCAB 26000
#define LRC 0.001f
#define MU0 (1.0f/39.0f)
#define RB 4

// pair kernel tiling
#define PR_ROWS 64
#define PR_CHUNK 16

// ---------------- scratch (device globals; no allocation) ----------------
__device__ float g_h[(size_t)BB * IN_DIM];   // [B, 2223]
__device__ float g_vx[(size_t)BB * FF * EE]; // [B, 39, 16]
__device__ float g_lin[BB];
__device__ float g_a1[IN_DIM];
__device__ float g_c1[IN_DIM];
__device__ float g_p1[2 * (size_t)BB * 100]; // fc1 split-K partials
__device__ float g_h2[BB * 100];
__device__ float g_p2s[64 * 100];
__device__ float g_p2q[64 * 100];
__device__ float g_a2[100];
__device__ float g_c2[100];
__device__ float g_h3[BB * 100];

// ---------------- meta kernel: gather + meta step + sparsemax + woff ------
__global__ __launch_bounds__(256) void meta_kernel(
    const int* __restrict__ x, const float* __restrict__ emb,
    const float* __restrict__ linw, const float* __restrict__ w0)
{
    __shared__ float s_vx[RB][FF][EE + 1];
    __shared__ float s_t [RB][FF][EE + 1];
    __shared__ float s_w1[RB][FF][FF];
    __shared__ float s_z [RB][FF];
    __shared__ float s_zs[RB][FF];
    __shared__ float s_mu[RB][FF];
    __shared__ float s_lv[RB][FF];
    __shared__ float s_tau[RB];

    const int tid = threadIdx.x;
    const int b0  = blockIdx.x * RB;

    for (int t = tid; t < RB * FF * 4; t += 256) {
        int r   = t / (FF * 4);
        int rem = t - r * (FF * 4);
        int f   = rem >> 2;
        int c   = rem & 3;
        int xi  = x[(b0 + r) * FF + f] + f * VOCAB;
        float4 v = reinterpret_cast<const float4*>(emb)[(size_t)xi * 4 + c];
        s_vx[r][f][c * 4 + 0] = v.x;
        s_vx[r][f][c * 4 + 1] = v.y;
        s_vx[r][f][c * 4 + 2] = v.z;
        s_vx[r][f][c * 4 + 3] = v.w;
        if (c == 0) s_lv[r][f] = linw[xi];
    }
    __syncthreads();

    // dump vx to global (coalesced) for the pair kernel
    for (int t = tid; t < RB * FF * EE; t += 256) {
        int r = t / (FF * EE);
        int q = t - r * (FF * EE);
        g_vx[(size_t)(b0 + r) * (FF * EE) + q] = s_vx[r][q / EE][q % EE];
    }

    // wv0 = w0 @ vx
    for (int t = tid; t < RB * FF * EE; t += 256) {
        int r = t / (FF * EE);
        int rem = t - r * (FF * EE);
        int i = rem / EE, e = rem - i * EE;
        float acc = 0.f;
        #pragma unroll
        for (int j = 0; j < FF; j++) acc = fmaf(w0[i * FF + j], s_vx[r][j][e], acc);
        s_t[r][i][e] = acc;
    }
    __syncthreads();

    // w1 = w0 - (LR*mu0) * (wv0 vx^T), diag = -1
    for (int t = tid; t < RB * FF * FF; t += 256) {
        int r = t / (FF * FF);
        int rem = t - r * (FF * FF);
        int i = rem / FF, j = rem - i * FF;
        float v;
        if (i == j) v = -1.0f;
        else {
            float d = 0.f;
            #pragma unroll
            for (int e = 0; e < EE; e++) d = fmaf(s_t[r][i][e], s_vx[r][j][e], d);
            v = w0[i * FF + j] - (LRC * MU0) * d;
        }
        s_w1[r][i][j] = v;
    }
    __syncthreads();

    // wv1 = w1 @ vx
    for (int t = tid; t < RB * FF * EE; t += 256) {
        int r = t / (FF * EE);
        int rem = t - r * (FF * EE);
        int i = rem / EE, e = rem - i * EE;
        float acc = 0.f;
        #pragma unroll
        for (int j = 0; j < FF; j++) acc = fmaf(s_w1[r][i][j], s_vx[r][j][e], acc);
        s_t[r][i][e] = acc;
    }
    __syncthreads();

    for (int t = tid; t < RB * FF; t += 256) {
        int r = t / FF, i = t - r * FF;
        float d = 0.f;
        #pragma unroll
        for (int e = 0; e < EE; e++) { float v = s_t[r][i][e]; d = fmaf(v, v, d); }
        s_z[r][i] = MU0 - LRC * 0.5f * d;
    }
    __syncthreads();

    for (int t = tid; t < RB * FF; t += 256) {
        int r = t / FF, i = t - r * FF;
        float zi = s_z[r][i];
        int rank = 0;
        #pragma unroll
        for (int j = 0; j < FF; j++) {
            float zj = s_z[r][j];
            rank += (zj > zi) || (zj == zi && j < i);
        }
        s_zs[r][rank] = zi;
    }
    __syncthreads();

    if (tid < RB) {
        int r = tid;
        float z0 = s_zs[r][0];
        float taus[FF];
        float cs = 0.f;
        #pragma unroll
        for (int j = 0; j < FF; j++) {
            cs += s_zs[r][j] - z0;
            taus[j] = (cs - 1.0f) / (float)(j + 1);
        }
        int k = 0;
        #pragma unroll
        for (int j = 0; j < FF; j++) k += (s_zs[r][j] - z0) > taus[j];
        s_tau[r] = taus[k - 1] + z0;

        float ls = 0.f;
        #pragma unroll
        for (int f = 0; f < FF; f++) ls += s_lv[r][f];
        g_lin[b0 + r] = ls;
    }
    __syncthreads();

    for (int t = tid; t < RB * FF; t += 256) {
        int r = t / FF, i = t - r * FF;
        s_mu[r][i] = fmaxf(s_z[r][i] - s_tau[r], 0.f);
    }
    __syncthreads();

    for (int t = tid; t < RB * WOFF_N; t += 256) {
        int r = t / WOFF_N;
        int m = t - r * WOFF_N;
        int fl = 1 + 40 * (m / 39) + (m % 39);
        int i = fl / 39, j = fl - i * 39;
        g_h[(size_t)(b0 + r) * IN_DIM + m] = s_mu[r][i] * s_w1[r][i][j];
    }
}

// ---------------- pair kernel: ox[b,p] = vx_i^T K_p vx_j ------------------
// block = 64 rows, 8 warps; warp owns a pair, lane owns rows (lane, lane+32).
// K staged in SMEM in 16-pair chunks; vx row-tile resident in SMEM.
__global__ __launch_bounds__(256, 1) void pair_kernel(const float* __restrict__ kern)
{
    extern __shared__ char smem[];
    float4* sVX = reinterpret_cast<float4*>(smem);                   // [39][4][64]
    float4* sK  = sVX + FF * 4 * PR_ROWS;                            // [16][64]
    float*  sOut = reinterpret_cast<float*>(sK + PR_CHUNK * 64);     // [16][65]

    const int tid  = threadIdx.x;
    const int wid  = tid >> 5;
    const int lane = tid & 31;
    const int b0   = blockIdx.x * PR_ROWS;

    // load vx tile: 64 rows x 156 float4, coalesced
    const float4* gvx4 = reinterpret_cast<const float4*>(g_vx);
    for (int t = tid; t < PR_ROWS * FF * 4; t += 256) {
        int row = t / (FF * 4);
        int q   = t - row * (FF * 4);          // q = f*4 + c
        sVX[q * PR_ROWS + row] = gvx4[(size_t)(b0 + row) * (FF * 4) + q];
    }

    const float4* kern4 = reinterpret_cast<const float4*>(kern);

    int pi_i = 0, pi_rem = FF - 1;   // running (i, pairs-left-for-i) for p0 base
    int base_i = 0, base_off = 0;    // i and offset of pair p0

    for (int p0 = 0; p0 < PP; p0 += PR_CHUNK) {
        int cnt = min(PR_CHUNK, PP - p0);
        __syncthreads();
        // stage K chunk
        for (int t = tid; t < cnt * 64; t += 256)
            sK[t] = kern4[(size_t)p0 * 64 + t];
        __syncthreads();

        for (int pi = wid; pi < cnt; pi += 8) {
            int p = p0 + pi;
            // decode (i, j) from p
            int i = 0, pp = p;
            while (pp >= FF - 1 - i) { pp -= FF - 1 - i; i++; }
            int j = i + 1 + pp;

            // load vx_i, vx_j for both rows
            float vi0[EE], vi1[EE], vj0[EE], vj1[EE];
            #pragma unroll
            for (int c = 0; c < 4; c++) {
                float4 a = sVX[(i * 4 + c) * PR_ROWS + lane];
                float4 b = sVX[(i * 4 + c) * PR_ROWS + lane + 32];
                vi0[c*4+0]=a.x; vi0[c*4+1]=a.y; vi0[c*4+2]=a.z; vi0[c*4+3]=a.w;
                vi1[c*4+0]=b.x; vi1[c*4+1]=b.y; vi1[c*4+2]=b.z; vi1[c*4+3]=b.w;
                float4 d = sVX[(j * 4 + c) * PR_ROWS + lane];
                float4 e = sVX[(j * 4 + c) * PR_ROWS + lane + 32];
                vj0[c*4+0]=d.x; vj0[c*4+1]=d.y; vj0[c*4+2]=d.z; vj0[c*4+3]=d.w;
                vj1[c*4+0]=e.x; vj1[c*4+1]=e.y; vj1[c*4+2]=e.z; vj1[c*4+3]=e.w;
            }

            float T0[EE], T1[EE];
            #pragma unroll
            for (int f2 = 0; f2 < EE; f2++) { T0[f2] = 0.f; T1[f2] = 0.f; }

            #pragma unroll 4
            for (int e = 0; e < EE; e++) {
                float kr[EE];
                #pragma unroll
                for (int c = 0; c < 4; c++) {
                    float4 kv = sK[pi * 64 + e * 4 + c];   // uniform broadcast
                    kr[c*4+0]=kv.x; kr[c*4+1]=kv.y; kr[c*4+2]=kv.z; kr[c*4+3]=kv.w;
                }
                float a0 = vi0[e], a1 = vi1[e];
                #pragma unroll
                for (int f2 = 0; f2 < EE; f2++) {
                    T0[f2] = fmaf(a0, kr[f2], T0[f2]);
                    T1[f2] = fmaf(a1, kr[f2], T1[f2]);
                }
            }
            float acc0 = 0.f, acc1 = 0.f;
            #pragma unroll
            for (int f2 = 0; f2 < EE; f2++) {
                acc0 = fmaf(T0[f2], vj0[f2], acc0);
                acc1 = fmaf(T1[f2], vj1[f2], acc1);
            }
            sOut[pi * (PR_ROWS + 1) + lane]      = acc0;
            sOut[pi * (PR_ROWS + 1) + lane + 32] = acc1;
        }
        __syncthreads();
        // flush chunk: consecutive p within a row -> 64B segments
        for (int t = tid; t < cnt * PR_ROWS; t += 256) {
            int row = t / cnt, pi = t - row * cnt;
            g_h[(size_t)(b0 + row) * IN_DIM + WOFF_N + p0 + pi] =
                sOut[pi * (PR_ROWS + 1) + row];
        }
    }
    (void)pi_i; (void)pi_rem; (void)base_i; (void)base_off;
}

// ---------------- BN1 column stats (deterministic) ------------------------
__global__ __launch_bounds__(256) void bn1_reduce(const float* __restrict__ gam,
                                                  const float* __restrict__ bet)
{
    __shared__ float shs[8][32];
    __shared__ float shq[8][32];
    int lane = threadIdx.x & 31;
    int rl   = threadIdx.x >> 5;
    int col  = blockIdx.x * 32 + lane;
    float s = 0.f, q = 0.f;
    if (col < IN_DIM) {
        for (int r = rl; r < BB; r += 8) {
            float v = g_h[(size_t)r * IN_DIM + col];
            s += v; q = fmaf(v, v, q);
        }
    }
    shs[rl][lane] = s; shq[rl][lane] = q;
    __syncthreads();
    if (rl == 0 && col < IN_DIM) {
        #pragma unroll
        for (int t = 1; t < 8; t++) { s += shs[t][lane]; q += shq[t][lane]; }
        float m   = s * (1.0f / BB);
        float var = q * (1.0f / BB) - m * m;
        float a   = gam[col] * rsqrtf(var + 1e-5f);
        g_a1[col] = a;
        g_c1[col] = bet[col] - m * a;
    }
}

// ---------------- fc1 GEMM (split-K=2, BM=128, 8x7 register tile) ---------
__global__ __launch_bounds__(256) void fc1_gemm(const float* __restrict__ W)
{
    __shared__ float sA[16][132];
    __shared__ float sW[16][113];
    const int bm = blockIdx.x * 128;
    const int ks = blockIdx.y;
    const int kbeg = ks ? 1112 : 0;
    const int kend = ks ? IN_DIM : 1112;
    const int tx = threadIdx.x & 15;
    const int ty = threadIdx.x >> 4;

    float acc[8][7];
    #pragma unroll
    for (int i2 = 0; i2 < 8; i2++)
        #pragma unroll
        for (int j2 = 0; j2 < 7; j2++) acc[i2][j2] = 0.f;

    for (int k0 = kbeg; k0 < kend; k0 += 16) {
        for (int t = threadIdx.x; t < 128 * 16; t += 256) {
            int m = t >> 4, kk = t & 15;
            int k = k0 + kk;
            float v = 0.f;
            if (k < kend) v = fmaf(g_h[(size_t)(bm + m) * IN_DIM + k], g_a1[k], g_c1[k]);
            sA[kk][m] = v;
        }
        for (int t = threadIdx.x; t < 112 * 16; t += 256) {
            int n = t >> 4, kk = t & 15;
            int k = k0 + kk;
            sW[kk][n] = (n < 100 && k < kend) ? W[n * IN_DIM + k] : 0.f;
        }
        __syncthreads();
        #pragma unroll
        for (int kk = 0; kk < 16; kk++) {
            float ra[8], rw[7];
            #pragma unroll
            for (int i2 = 0; i2 < 8; i2++) ra[i2] = sA[kk][ty + 16 * i2];
            #pragma unroll
            for (int j2 = 0; j2 < 7; j2++) rw[j2] = sW[kk][tx + 16 * j2];
            #pragma unroll
            for (int i2 = 0; i2 < 8; i2++)
                #pragma unroll
                for (int j2 = 0; j2 < 7; j2++)
                    acc[i2][j2] = fmaf(ra[i2], rw[j2], acc[i2][j2]);
        }
        __syncthreads();
    }
    float* dst = g_p1 + (size_t)ks * BB * 100;
    #pragma unroll
    for (int i2 = 0; i2 < 8; i2++) {
        int m = bm + ty + 16 * i2;
        #pragma unroll
        for (int j2 = 0; j2 < 7; j2++) {
            int n = tx + 16 * j2;
            if (n < 100) dst[(size_t)m * 100 + n] = acc[i2][j2];
        }
    }
}

__global__ __launch_bounds__(256) void fc1_combine(const float* __restrict__ bias)
{
    int t = blockIdx.x * 256 + threadIdx.x;
    if (t < BB * 100) {
        int n = t % 100;
        float v = g_p1[t] + g_p1[(size_t)BB * 100 + t] + bias[n];
        g_h2[t] = fmaxf(v, 0.f);
    }
}

// ---------------- small GEMM for fc2: out = relu((A*a+c) @ W^T + b) -------
__global__ __launch_bounds__(256) void mlp_gemm(
    const float* __restrict__ A, int K,
    const float* __restrict__ avec, const float* __restrict__ cvec,
    const float* __restrict__ W, const float* __restrict__ bias,
    float* __restrict__ out)
{
    __shared__ float sA[16][65];
    __shared__ float sW[16][113];
    const int bm = blockIdx.x * 64;
    const int tx = threadIdx.x & 15;
    const int ty = threadIdx.x >> 4;
    float acc[4][7];
    #pragma unroll
    for (int i2 = 0; i2 < 4; i2++)
        #pragma unroll
        for (int j2 = 0; j2 < 7; j2++) acc[i2][j2] = 0.f;

    for (int k0 = 0; k0 < K; k0 += 16) {
        for (int t = threadIdx.x; t < 64 * 16; t += 256) {
            int m = t >> 4, kk = t & 15;
            int k = k0 + kk;
            float v = 0.f;
            if (k < K) v = fmaf(A[(size_t)(bm + m) * K + k], avec[k], cvec[k]);
            sA[kk][m] = v;
        }
        for (int t = threadIdx.x; t < 112 * 16; t += 256) {
            int n = t >> 4, kk = t & 15;
            int k = k0 + kk;
            sW[kk][n] = (n < 100 && k < K) ? W[n * K + k] : 0.f;
        }
        __syncthreads();
        #pragma unroll
        for (int kk = 0; kk < 16; kk++) {
            float ra[4], rw[7];
            #pragma unroll
            for (int i2 = 0; i2 < 4; i2++) ra[i2] = sA[kk][ty + 16 * i2];
            #pragma unroll
            for (int j2 = 0; j2 < 7; j2++) rw[j2] = sW[kk][tx + 16 * j2];
            #pragma unroll
            for (int i2 = 0; i2 < 4; i2++)
                #pragma unroll
                for (int j2 = 0; j2 < 7; j2++)
                    acc[i2][j2] = fmaf(ra[i2], rw[j2], acc[i2][j2]);
        }
        __syncthreads();
    }
    #pragma unroll
    for (int i2 = 0; i2 < 4; i2++) {
        int m = bm + ty + 16 * i2;
        #pragma unroll
        for (int j2 = 0; j2 < 7; j2++) {
            int n = tx + 16 * j2;
            if (n < 100) out[m * 100 + n] = fmaxf(acc[i2][j2] + bias[n], 0.f);
        }
    }
}

// ---------------- BN2 two-level deterministic reduction -------------------
__global__ __launch_bounds__(128) void bn2_partial()
{
    int c  = threadIdx.x;
    int r0 = blockIdx.x * 256;
    if (c < 100) {
        float s = 0.f, q = 0.f;
        for (int r = r0; r < r0 + 256; r++) {
            float v = g_h2[r * 100 + c];
            s += v; q = fmaf(v, v, q);
        }
        g_p2s[blockIdx.x * 100 + c] = s;
        g_p2q[blockIdx.x * 100 + c] = q;
    }
}

__global__ __launch_bounds__(128) void bn2_final(const float* __restrict__ gam,
                                                 const float* __restrict__ bet)
{
    int c = threadIdx.x;
    if (c < 100) {
        float s = 0.f, q = 0.f;
        for (int i = 0; i < 64; i++) { s += g_p2s[i * 100 + c]; q += g_p2q[i * 100 + c]; }
        float m   = s * (1.0f / BB);
        float var = q * (1.0f / BB) - m * m;
        float a   = gam[c] * rsqrtf(var + 1e-5f);
        g_a2[c] = a;
        g_c2[c] = bet[c] - m * a;
    }
}

// ---------------- fc3 + lin ----------------------------------------------
__global__ __launch_bounds__(256) void out_kernel(const float* __restrict__ w3,
                                                  const float* __restrict__ b3,
                                                  float* __restrict__ out)
{
    int wrp  = (blockIdx.x * 256 + threadIdx.x) >> 5;
    int lane = threadIdx.x & 31;
    if (wrp < BB) {
        float s = 0.f;
        for (int k = lane; k < 100; k += 32)
            s = fmaf(g_h3[wrp * 100 + k], w3[k], s);
        #pragma unroll
        for (int o = 16; o > 0; o >>= 1) s += __shfl_xor_sync(0xffffffffu, s, o);
        if (lane == 0) out[wrp] = s + b3[0] + g_lin[wrp];
    }
}

// ---------------- launch ---------------------------------------------------
extern "C" void kernel_launch(void* const* d_in, const int* in_sizes, int n_in,
                              void* d_out, int out_size)
{
    const int*   x     = (const int*)  d_in[0];
    const float* emb   = (const float*)d_in[1];
    const float* linw  = (const float*)d_in[2];
    const float* w0    = (const float*)d_in[3];
    const float* kern  = (const float*)d_in[4];
    const float* bn1g  = (const float*)d_in[5];
    const float* bn1b  = (const float*)d_in[6];
    const float* fc1w  = (const float*)d_in[7];
    const float* fc1b  = (const float*)d_in[8];
    const float* bn2g  = (const float*)d_in[9];
    const float* bn2b  = (const float*)d_in[10];
    const float* fc2w  = (const float*)d_in[11];
    const float* fc2b  = (const float*)d_in[12];
    const float* fc3w  = (const float*)d_in[13];
    const float* fc3b  = (const float*)d_in[14];
    float* out = (float*)d_out;
    (void)in_sizes; (void)n_in; (void)out_size;

    float *gh2, *gh3, *ga2, *gc2;
    cudaGetSymbolAddress((void**)&gh2, g_h2);
    cudaGetSymbolAddress((void**)&gh3, g_h3);
    cudaGetSymbolAddress((void**)&ga2, g_a2);
    cudaGetSymbolAddress((void**)&gc2, g_c2);

    // pair kernel dynamic smem: vx tile + K chunk + out staging
    const int smem_pair = (FF * 4 * PR_ROWS + PR_CHUNK * 64) * 16
                        + PR_CHUNK * (PR_ROWS + 1) * 4;
    cudaFuncSetAttribute(pair_kernel, cudaFuncAttributeMaxDynamicSharedMemorySize,
                         smem_pair);

    meta_kernel <<<BB / RB, 256>>>(x, emb, linw, w0);
    pair_kernel <<<BB / PR_ROWS, 256, smem_pair>>>(kern);
    bn1_reduce  <<<(IN_DIM + 31) / 32, 256>>>(bn1g, bn1b);
    {
        dim3 g(BB / 128, 2);
        fc1_gemm <<<g, 256>>>(fc1w);
    }
    fc1_combine <<<(BB * 100 + 255) / 256, 256>>>(fc1b);
    bn2_partial <<<64, 128>>>();
    bn2_final   <<<1, 128>>>(bn2g, bn2b);
    mlp_gemm    <<<BB / 64, 256>>>(gh2, 100, ga2, gc2, fc2w, fc2b, gh3);
    out_kernel  <<<(BB * 32 + 255) / 256, 256>>>(fc3w, fc3b, out);
}